// round 8
// baseline (speedup 1.0000x reference)
#include <cuda_runtime.h>

// BettingLoss: B=4194304 rows, T=6 traps, 3 x f32 [B,T] inputs.
// Single fused streaming-reduction kernel -> [loss, batch_profit, num_bets].
// SINGLE-WAVE persistent grid: 912 blocks = 152 SMs x 6 resident blocks
// (40 regs, 256 thr) -> no wave-quantization tail. Streaming loads (__ldcs).

#define TPB   256
#define NBLK  912          // 152 SMs * 6 blocks/SM -> exactly one wave on GB300

static constexpr int   B_ROWS  = 4194304;
static constexpr float PAYOUT  = (float)(0.02 * 0.95);          // bet_pct*(1-comm) = 0.019
static constexpr float K_EP    = (float)(1.1 * 0.02 * 0.95);    // alpha*payout     = 0.0209

__device__ float4       g_part[NBLK];  // x=sum_bet_ep, y=sum_profit, z=num_bets, w=sum_maxp
__device__ unsigned int g_count = 0;

__device__ __forceinline__ float4 warp_reduce4(float4 v)
{
#pragma unroll
    for (int off = 16; off > 0; off >>= 1) {
        v.x += __shfl_down_sync(0xffffffffu, v.x, off);
        v.y += __shfl_down_sync(0xffffffffu, v.y, off);
        v.z += __shfl_down_sync(0xffffffffu, v.z, off);
        v.w += __shfl_down_sync(0xffffffffu, v.w, off);
    }
    return v;
}

__global__ void __launch_bounds__(TPB, 6)
betting_fused(const float* __restrict__ pp,
              const float* __restrict__ tw,
              const float* __restrict__ mo,
              float* __restrict__ out, int out_size)
{
    float s_ep = 0.0f, s_pr = 0.0f, s_nb = 0.0f, s_mx = 0.0f;

    const unsigned tid = blockIdx.x * TPB + threadIdx.x;
    const unsigned TOT = NBLK * TPB;           // 233472 threads; ~18 rows/thread

#pragma unroll 2
    for (unsigned r = tid; r < (unsigned)B_ROWS; r += TOT) {
        size_t base = (size_t)r * 6u;          // 6 floats = 1 row, 8B aligned

        const float2* p2 = (const float2*)(pp + base);
        const float2* w2 = (const float2*)(tw + base);
        const float2* o2 = (const float2*)(mo + base);

        float2 pa = __ldcs(p2 + 0), pb = __ldcs(p2 + 1), pc = __ldcs(p2 + 2);
        float2 oa = __ldcs(o2 + 0), ob = __ldcs(o2 + 1), oc = __ldcs(o2 + 2);
        float2 wa = __ldcs(w2 + 0), wb = __ldcs(w2 + 1), wc = __ldcs(w2 + 2);

        // fallback term: max predicted prob
        s_mx += fmaxf(fmaxf(fmaxf(pa.x, pa.y), fmaxf(pb.x, pb.y)),
                      fmaxf(pc.x, pc.y));

        // argmax of ep == argmax of q = mo*pp (ep affine increasing in q).
        // has_valid is redundant: all-zero odds -> q_max = 0 -> best_ep < 0 -> no bet.
        float q0 = oa.x * pa.x, q1 = oa.y * pa.y;
        float q2 = ob.x * pb.x, q3 = ob.y * pb.y;
        float q4 = oc.x * pc.x, q5 = oc.y * pc.y;

        float bq = q0, bo = oa.x, bw = wa.x;
        bool g;
        g = q1 > bq; bq = g ? q1 : bq; bo = g ? oa.y : bo; bw = g ? wa.y : bw;
        g = q2 > bq; bq = g ? q2 : bq; bo = g ? ob.x : bo; bw = g ? wb.x : bw;
        g = q3 > bq; bq = g ? q3 : bq; bo = g ? ob.y : bo; bw = g ? wb.y : bw;
        g = q4 > bq; bq = g ? q4 : bq; bo = g ? oc.x : bo; bw = g ? wc.x : bw;
        g = q5 > bq; bq = g ? q5 : bq; bo = g ? oc.y : bo; bw = g ? wc.y : bw;

        float best_ep = fmaf(bq, K_EP, -PAYOUT);
        if (best_ep > 0.0f) {
            s_ep += best_ep;
            s_nb += 1.0f;
            s_pr += (bw > 0.5f) ? fmaf(bo, K_EP, -PAYOUT) : -PAYOUT;
        }
    }

    // ---- block reduce ----
    float4 v = warp_reduce4(make_float4(s_ep, s_pr, s_nb, s_mx));

    __shared__ float4 sm[TPB / 32];
    const int lane = threadIdx.x & 31;
    const int warp = threadIdx.x >> 5;
    if (lane == 0) sm[warp] = v;
    __syncthreads();

    __shared__ bool isLast;
    if (warp == 0) {
        float4 b = (lane < TPB / 32) ? sm[lane] : make_float4(0.f, 0.f, 0.f, 0.f);
#pragma unroll
        for (int off = (TPB / 32) / 2; off > 0; off >>= 1) {
            b.x += __shfl_down_sync(0xffffffffu, b.x, off);
            b.y += __shfl_down_sync(0xffffffffu, b.y, off);
            b.z += __shfl_down_sync(0xffffffffu, b.z, off);
            b.w += __shfl_down_sync(0xffffffffu, b.w, off);
        }
        if (lane == 0) {
            g_part[blockIdx.x] = b;
            __threadfence();
            unsigned prev = atomicAdd(&g_count, 1u);
            isLast = (prev == NBLK - 1u);
        }
    }
    __syncthreads();
    if (!isLast) return;

    // ---- last block: final reduce of NBLK partials ----
    float4 acc = make_float4(0.f, 0.f, 0.f, 0.f);
    for (int i = threadIdx.x; i < NBLK; i += TPB) {
        float4 p = g_part[i];
        acc.x += p.x; acc.y += p.y; acc.z += p.z; acc.w += p.w;
    }
    acc = warp_reduce4(acc);
    if (lane == 0) sm[warp] = acc;
    __syncthreads();

    if (warp == 0) {
        float4 b = (lane < TPB / 32) ? sm[lane] : make_float4(0.f, 0.f, 0.f, 0.f);
#pragma unroll
        for (int off = (TPB / 32) / 2; off > 0; off >>= 1) {
            b.x += __shfl_down_sync(0xffffffffu, b.x, off);
            b.y += __shfl_down_sync(0xffffffffu, b.y, off);
            b.z += __shfl_down_sync(0xffffffffu, b.z, off);
            b.w += __shfl_down_sync(0xffffffffu, b.w, off);
        }
        if (lane == 0) {
            const float invB = 1.0f / (float)B_ROWS;   // B = 2^22: exact
            float fallback = -(b.w * invB) * 0.1f;
            float tep  = (b.z > 0.0f) ? b.x : fallback;
            float loss = -tep * invB;

            if (out_size > 0) out[0] = loss;
            if (out_size > 1) out[1] = b.y;
            if (out_size > 2) out[2] = b.z;

            g_count = 0;                               // reset for next graph replay
        }
    }
}

extern "C" void kernel_launch(void* const* d_in, const int* in_sizes, int n_in,
                              void* d_out, int out_size)
{
    const float* pp = (const float*)d_in[0];   // predicted_probs [B,T]
    const float* tw = (const float*)d_in[1];   // true_winners    [B,T]
    const float* mo = (const float*)d_in[2];   // market_odds     [B,T]

    betting_fused<<<NBLK, TPB>>>(pp, tw, mo, (float*)d_out, out_size);
}

// round 9
// speedup vs baseline: 1.0185x; 1.0185x over previous
#include <cuda_runtime.h>

// BettingLoss: B=4194304 rows, T=6 traps, 3 x f32 [B,T] inputs.
// Single fused streaming-reduction kernel -> [loss, batch_profit, num_bets].
// At ~6.07 TB/s this sits at ~95% of the GB300 path-independent LTS cap
// (~6300 B/cyc full-chip); occupancy / wave shape / load width all proven
// non-binding (R6-R8). This config is the best-measured launch shape.

#define TPB   256
#define NBLK  2048
#define NITER 8            // B / (NBLK*TPB) = 8 exactly (compile-time trip count)

static constexpr int   B_ROWS  = 4194304;
static constexpr float PAYOUT  = (float)(0.02 * 0.95);          // bet_pct*(1-comm) = 0.019
static constexpr float K_EP    = (float)(1.1 * 0.02 * 0.95);    // alpha*payout     = 0.0209

__device__ float4       g_part[NBLK];  // x=sum_bet_ep, y=sum_profit, z=num_bets, w=sum_maxp
__device__ unsigned int g_count = 0;

__device__ __forceinline__ float4 warp_reduce4(float4 v)
{
#pragma unroll
    for (int off = 16; off > 0; off >>= 1) {
        v.x += __shfl_down_sync(0xffffffffu, v.x, off);
        v.y += __shfl_down_sync(0xffffffffu, v.y, off);
        v.z += __shfl_down_sync(0xffffffffu, v.z, off);
        v.w += __shfl_down_sync(0xffffffffu, v.w, off);
    }
    return v;
}

__global__ void __launch_bounds__(TPB, 6)
betting_fused(const float* __restrict__ pp,
              const float* __restrict__ tw,
              const float* __restrict__ mo,
              float* __restrict__ out, int out_size)
{
    float s_ep = 0.0f, s_pr = 0.0f, s_nb = 0.0f, s_mx = 0.0f;

    const unsigned tid = blockIdx.x * TPB + threadIdx.x;
    const unsigned TOT = NBLK * TPB;           // 524288 threads; 8 rows/thread exactly

#pragma unroll 2
    for (int it = 0; it < NITER; it++) {
        size_t base = (size_t)(tid + (unsigned)it * TOT) * 6u;   // 6 floats = 1 row, 8B aligned

        const float2* p2 = (const float2*)(pp + base);
        const float2* w2 = (const float2*)(tw + base);
        const float2* o2 = (const float2*)(mo + base);

        float2 pa = p2[0], pb = p2[1], pc = p2[2];
        float2 oa = o2[0], ob = o2[1], oc = o2[2];
        float2 wa = w2[0], wb = w2[1], wc = w2[2];

        // fallback term: max predicted prob
        s_mx += fmaxf(fmaxf(fmaxf(pa.x, pa.y), fmaxf(pb.x, pb.y)),
                      fmaxf(pc.x, pc.y));

        // argmax of ep == argmax of q = mo*pp (ep affine increasing in q).
        // has_valid is redundant: all-zero odds -> q_max = 0 -> best_ep < 0 -> no bet.
        float q0 = oa.x * pa.x, q1 = oa.y * pa.y;
        float q2 = ob.x * pb.x, q3 = ob.y * pb.y;
        float q4 = oc.x * pc.x, q5 = oc.y * pc.y;

        float bq = q0, bo = oa.x, bw = wa.x;
        bool g;
        g = q1 > bq; bq = g ? q1 : bq; bo = g ? oa.y : bo; bw = g ? wa.y : bw;
        g = q2 > bq; bq = g ? q2 : bq; bo = g ? ob.x : bo; bw = g ? wb.x : bw;
        g = q3 > bq; bq = g ? q3 : bq; bo = g ? ob.y : bo; bw = g ? wb.y : bw;
        g = q4 > bq; bq = g ? q4 : bq; bo = g ? oc.x : bo; bw = g ? wc.x : bw;
        g = q5 > bq; bq = g ? q5 : bq; bo = g ? oc.y : bo; bw = g ? wc.y : bw;

        float best_ep = fmaf(bq, K_EP, -PAYOUT);
        if (best_ep > 0.0f) {
            s_ep += best_ep;
            s_nb += 1.0f;
            s_pr += (bw > 0.5f) ? fmaf(bo, K_EP, -PAYOUT) : -PAYOUT;
        }
    }

    // ---- block reduce ----
    float4 v = warp_reduce4(make_float4(s_ep, s_pr, s_nb, s_mx));

    __shared__ float4 sm[TPB / 32];
    const int lane = threadIdx.x & 31;
    const int warp = threadIdx.x >> 5;
    if (lane == 0) sm[warp] = v;
    __syncthreads();

    __shared__ bool isLast;
    if (warp == 0) {
        float4 b = (lane < TPB / 32) ? sm[lane] : make_float4(0.f, 0.f, 0.f, 0.f);
#pragma unroll
        for (int off = (TPB / 32) / 2; off > 0; off >>= 1) {
            b.x += __shfl_down_sync(0xffffffffu, b.x, off);
            b.y += __shfl_down_sync(0xffffffffu, b.y, off);
            b.z += __shfl_down_sync(0xffffffffu, b.z, off);
            b.w += __shfl_down_sync(0xffffffffu, b.w, off);
        }
        if (lane == 0) {
            g_part[blockIdx.x] = b;
            __threadfence();
            unsigned prev = atomicAdd(&g_count, 1u);
            isLast = (prev == NBLK - 1u);
        }
    }
    __syncthreads();
    if (!isLast) return;

    // ---- last block: final reduce of NBLK partials ----
    float4 acc = make_float4(0.f, 0.f, 0.f, 0.f);
#pragma unroll
    for (int i = 0; i < NBLK / TPB; i++) {
        float4 p = g_part[threadIdx.x + i * TPB];
        acc.x += p.x; acc.y += p.y; acc.z += p.z; acc.w += p.w;
    }
    acc = warp_reduce4(acc);
    if (lane == 0) sm[warp] = acc;
    __syncthreads();

    if (warp == 0) {
        float4 b = (lane < TPB / 32) ? sm[lane] : make_float4(0.f, 0.f, 0.f, 0.f);
#pragma unroll
        for (int off = (TPB / 32) / 2; off > 0; off >>= 1) {
            b.x += __shfl_down_sync(0xffffffffu, b.x, off);
            b.y += __shfl_down_sync(0xffffffffu, b.y, off);
            b.z += __shfl_down_sync(0xffffffffu, b.z, off);
            b.w += __shfl_down_sync(0xffffffffu, b.w, off);
        }
        if (lane == 0) {
            const float invB = 1.0f / (float)B_ROWS;   // B = 2^22: exact
            float fallback = -(b.w * invB) * 0.1f;
            float tep  = (b.z > 0.0f) ? b.x : fallback;
            float loss = -tep * invB;

            if (out_size > 0) out[0] = loss;
            if (out_size > 1) out[1] = b.y;
            if (out_size > 2) out[2] = b.z;

            g_count = 0;                               // reset for next graph replay
        }
    }
}

extern "C" void kernel_launch(void* const* d_in, const int* in_sizes, int n_in,
                              void* d_out, int out_size)
{
    const float* pp = (const float*)d_in[0];   // predicted_probs [B,T]
    const float* tw = (const float*)d_in[1];   // true_winners    [B,T]
    const float* mo = (const float*)d_in[2];   // market_odds     [B,T]

    betting_fused<<<NBLK, TPB>>>(pp, tw, mo, (float*)d_out, out_size);
}